// round 1
// baseline (speedup 1.0000x reference)
#include <cuda_runtime.h>
#include <math.h>

// Problem shape (fixed by the dataset)
#define W_ 160
#define H_ 128
#define C_ 32
#define G_ 8
#define D_ 48
#define S_ 2
#define HW_ (H_ * W_)

// Scratch (no cudaMalloc allowed): precomputed softmax of ref features (CHW layout)
__device__ float g_refsm[C_ * HW_];
// Per-source rotation (row-major 3x3) and translation of proj = src_proj @ inv(ref_proj)
__device__ float g_rot[S_][9];
__device__ float g_trans[S_][3];
// Folded depth-weight MLP constants
__device__ float g_w1[G_];
__device__ float g_aff[4];  // s1, c1, w2, b2

// ---------------------------------------------------------------------------
// Prep 1: single thread. 4x4 inverse (Gauss-Jordan, double), matrix products,
// BN affine fold.
// ---------------------------------------------------------------------------
__global__ void prep_params_kernel(const float* __restrict__ ref_proj,
                                   const float* __restrict__ src_projs,
                                   const float* __restrict__ w1,
                                   const float* __restrict__ bn_gamma,
                                   const float* __restrict__ bn_beta,
                                   const float* __restrict__ bn_mean,
                                   const float* __restrict__ bn_var,
                                   const float* __restrict__ w2,
                                   const float* __restrict__ b2) {
    // inv(ref_proj) via Gauss-Jordan with partial pivoting (double precision)
    double a[4][8];
    for (int i = 0; i < 4; i++)
        for (int j = 0; j < 4; j++) {
            a[i][j] = (double)ref_proj[i * 4 + j];
            a[i][4 + j] = (i == j) ? 1.0 : 0.0;
        }
    for (int col = 0; col < 4; col++) {
        int piv = col;
        double best = fabs(a[col][col]);
        for (int r = col + 1; r < 4; r++) {
            double v = fabs(a[r][col]);
            if (v > best) { best = v; piv = r; }
        }
        if (piv != col)
            for (int j = 0; j < 8; j++) {
                double tmp = a[col][j]; a[col][j] = a[piv][j]; a[piv][j] = tmp;
            }
        double inv = 1.0 / a[col][col];
        for (int j = 0; j < 8; j++) a[col][j] *= inv;
        for (int r = 0; r < 4; r++) {
            if (r == col) continue;
            double f = a[r][col];
            for (int j = 0; j < 8; j++) a[r][j] -= f * a[col][j];
        }
    }
    // proj[s] = src_projs[s] @ inv(ref_proj); keep rot (3x3) + trans (3x1)
    for (int s = 0; s < S_; s++) {
        const float* sp = src_projs + s * 16;
        double proj[3][4];
        for (int i = 0; i < 3; i++)
            for (int j = 0; j < 4; j++) {
                double acc = 0.0;
                for (int k = 0; k < 4; k++)
                    acc += (double)sp[i * 4 + k] * a[k][4 + j];
                proj[i][j] = acc;
            }
        for (int i = 0; i < 3; i++) {
            for (int j = 0; j < 3; j++) g_rot[s][i * 3 + j] = (float)proj[i][j];
            g_trans[s][i] = (float)proj[i][3];
        }
    }
    for (int g = 0; g < G_; g++) g_w1[g] = w1[g];
    double s1 = (double)bn_gamma[0] / sqrt((double)bn_var[0] + 1e-5);
    double c1 = (double)bn_beta[0] - (double)bn_mean[0] * s1;
    g_aff[0] = (float)s1;
    g_aff[1] = (float)c1;
    g_aff[2] = w2[0];
    g_aff[3] = b2[0];
}

// ---------------------------------------------------------------------------
// Prep 2: softmax over the 4 channels of each group of the ref feature.
// One thread per (group, pixel). Coalesced over pixels.
// ---------------------------------------------------------------------------
__global__ __launch_bounds__(256) void ref_softmax_kernel(const float* __restrict__ ref) {
    int t = blockIdx.x * blockDim.x + threadIdx.x;
    if (t >= G_ * HW_) return;
    int p = t % HW_;
    int g = t / HW_;
    const float* b = ref + (g * 4) * HW_ + p;
    float v0 = b[0], v1 = b[HW_], v2 = b[2 * HW_], v3 = b[3 * HW_];
    float m = fmaxf(fmaxf(v0, v1), fmaxf(v2, v3));
    float e0 = __expf(v0 - m), e1 = __expf(v1 - m);
    float e2 = __expf(v2 - m), e3 = __expf(v3 - m);
    float is = __fdividef(1.0f, (e0 + e1) + (e2 + e3));
    float* o = g_refsm + (g * 4) * HW_ + p;
    o[0] = e0 * is;
    o[HW_] = e1 * is;
    o[2 * HW_] = e2 * is;
    o[3 * HW_] = e3 * is;
}

// ---------------------------------------------------------------------------
// Main fused kernel: one thread per (d, h, w). For both sources: project,
// bilinear-gather 32 channels, per-group softmax dotted with ref softmax,
// depth-weight sigmoid, weighted combine. Writes out[g][d][h][w].
// ---------------------------------------------------------------------------
__global__ __launch_bounds__(256) void fuse_kernel(const float* __restrict__ srcF,
                                                   const float* __restrict__ depths,
                                                   float* __restrict__ out) {
    int t = blockIdx.x * blockDim.x + threadIdx.x;
    if (t >= D_ * HW_) return;
    int p = t % HW_;
    int d = t / HW_;
    int x = p % W_;
    int y = p / W_;
    float xf = (float)x, yf = (float)y;
    float depth = depths[d];

    // Per-source bilinear corner weights (folded with validity) and bases
    float ew[S_][4];
    int bi[S_][4];
#pragma unroll
    for (int s = 0; s < S_; s++) {
        float r00 = g_rot[s][0], r01 = g_rot[s][1], r02 = g_rot[s][2];
        float r10 = g_rot[s][3], r11 = g_rot[s][4], r12 = g_rot[s][5];
        float r20 = g_rot[s][6], r21 = g_rot[s][7], r22 = g_rot[s][8];
        float X = fmaf(fmaf(r00, xf, fmaf(r01, yf, r02)), depth, g_trans[s][0]);
        float Y = fmaf(fmaf(r10, xf, fmaf(r11, yf, r12)), depth, g_trans[s][1]);
        float Z = fmaf(fmaf(r20, xf, fmaf(r21, yf, r22)), depth, g_trans[s][2]);
        float iz = __fdividef(1.0f, Z);
        float px = X * iz;
        float py = Y * iz;
        float x0f = floorf(px), y0f = floorf(py);
        float wx = px - x0f, wy = py - y0f;
#pragma unroll
        for (int k = 0; k < 4; k++) {
            int dx = k & 1, dy = k >> 1;
            float cx = x0f + (float)dx;
            float cy = y0f + (float)dy;
            bool valid = (cx >= 0.0f) && (cx <= (float)(W_ - 1)) &&
                         (cy >= 0.0f) && (cy <= (float)(H_ - 1));
            float wt = (dx ? wx : 1.0f - wx) * (dy ? wy : 1.0f - wy);
            ew[s][k] = valid ? wt : 0.0f;
            int xi = min(max((int)cx, 0), W_ - 1);
            int yi = min(max((int)cy, 0), H_ - 1);
            bi[s][k] = yi * W_ + xi;
        }
    }

    float v[S_][G_];
    float lin0 = 0.0f, lin1 = 0.0f;
    const float* rs = g_refsm + p;

#pragma unroll
    for (int g = 0; g < G_; g++) {
        float r0 = rs[(4 * g + 0) * HW_];
        float r1 = rs[(4 * g + 1) * HW_];
        float r2 = rs[(4 * g + 2) * HW_];
        float r3 = rs[(4 * g + 3) * HW_];
#pragma unroll
        for (int s = 0; s < S_; s++) {
            const float* sb = srcF + (s * C_ + 4 * g) * HW_;
            float a0 = 0.0f, a1 = 0.0f, a2 = 0.0f, a3 = 0.0f;
#pragma unroll
            for (int k = 0; k < 4; k++) {
                float wq = ew[s][k];
                if (wq != 0.0f) {
                    const float* q = sb + bi[s][k];
                    a0 = fmaf(wq, q[0], a0);
                    a1 = fmaf(wq, q[HW_], a1);
                    a2 = fmaf(wq, q[2 * HW_], a2);
                    a3 = fmaf(wq, q[3 * HW_], a3);
                }
            }
            float m = fmaxf(fmaxf(a0, a1), fmaxf(a2, a3));
            float e0 = __expf(a0 - m), e1 = __expf(a1 - m);
            float e2 = __expf(a2 - m), e3 = __expf(a3 - m);
            float ssum = (e0 + e1) + (e2 + e3);
            float num = fmaf(e0, r0, fmaf(e1, r1, fmaf(e2, r2, e3 * r3)));
            float vv = __fdividef(num, ssum);
            v[s][g] = vv;
            if (s == 0) lin0 = fmaf(g_w1[g], vv, lin0);
            else        lin1 = fmaf(g_w1[g], vv, lin1);
        }
    }

    float s1 = g_aff[0], c1 = g_aff[1], w2c = g_aff[2], b2c = g_aff[3];
    float wgt[S_];
    float lin[S_] = {lin0, lin1};
#pragma unroll
    for (int s = 0; s < S_; s++) {
        float bn = fmaf(lin[s], s1, c1);
        float ac = fmaf(fmaxf(bn, 0.0f), w2c, b2c);
        wgt[s] = __fdividef(1.0f, 1.0f + __expf(-ac));
    }
    float iw = __fdividef(1.0f, wgt[0] + wgt[1]);
#pragma unroll
    for (int g = 0; g < G_; g++) {
        out[(g * D_ + d) * HW_ + p] =
            (wgt[0] * v[0][g] + wgt[1] * v[1][g]) * iw;
    }
}

// ---------------------------------------------------------------------------
// Launch
// ---------------------------------------------------------------------------
extern "C" void kernel_launch(void* const* d_in, const int* in_sizes, int n_in,
                              void* d_out, int out_size) {
    const float* ref_feature = (const float*)d_in[0];
    const float* src_features = (const float*)d_in[1];
    const float* ref_proj = (const float*)d_in[2];
    const float* src_projs = (const float*)d_in[3];
    const float* depth_hypos = (const float*)d_in[4];
    const float* w1 = (const float*)d_in[5];
    const float* bn_gamma = (const float*)d_in[6];
    const float* bn_beta = (const float*)d_in[7];
    const float* bn_mean = (const float*)d_in[8];
    const float* bn_var = (const float*)d_in[9];
    const float* w2 = (const float*)d_in[10];
    const float* b2 = (const float*)d_in[11];
    float* out = (float*)d_out;

    prep_params_kernel<<<1, 1>>>(ref_proj, src_projs, w1, bn_gamma, bn_beta,
                                 bn_mean, bn_var, w2, b2);

    int n_ref = G_ * HW_;
    ref_softmax_kernel<<<(n_ref + 255) / 256, 256>>>(ref_feature);

    int n_main = D_ * HW_;
    fuse_kernel<<<(n_main + 255) / 256, 256>>>(src_features, depth_hypos, out);
}